// round 10
// baseline (speedup 1.0000x reference)
#include <cuda_runtime.h>
#include <cstdint>

#define MARGIN 0.1f
#define NANF_U 0x7fffffffu

#define TI 512    // i per block (NI * BI)
#define TJ 64     // j per block
#define BI 256    // threads
#define NI 2      // i rows per thread
#define RT (TI / TJ)   // band width in j-tiles per i-tile row = 8

// Cross-block state; last block resets g_done/g_cnt each launch (graph-safe).
__device__ float        g_part[4096];
__device__ int          g_cnt;
__device__ unsigned int g_done;

// s = sign(dt) * dp : copy dt's sign bit onto dp via one LOP3. NaN-preserving.
__device__ __forceinline__ float sign_mul(float dp, float dt) {
    return __uint_as_float(__float_as_uint(dp) ^
                           (__float_as_uint(dt) & 0x80000000u));
}

// Triangle-tiled sweep. Blocks enumerate (i-tile r, j-tile) with j-tile >= RT*r.
//  - band block  (j0 <  i0+TI): full rectangle, weight 1 (same-tile unordered
//    pairs appear in two band blocks -> weight 2; diagonal once)
//  - upper block (j0 >= i0+TI): weight 2
// Per evaluated slot accumulate x = min(sign(dt)*dp, MARGIN):
//  valid -> min(s,m); masked/OOB (p=NaN) -> m; unmasked diag -> 0.
// Then sum_hinge = m*(N*N - nv) - A,  count = nv*(nv-1).
__global__ void __launch_bounds__(BI, 7)
mrl_pair(const float* __restrict__ p,
         const float* __restrict__ t,
         const int* __restrict__ m,
         int B, int n64, float* __restrict__ out) {
    __shared__ float4 sj[TJ / 2];      // {-t0, -p0, -t1, -p1} per pair of j
    __shared__ float red_s[BI / 32];
    __shared__ int   red_c[BI / 32];
    __shared__ int   s_is_last;

    const int tid = threadIdx.x;
    const float NANF = __uint_as_float(NANF_U);

    // Decode linear block id -> (i-tile r, j-tile). Row r owns n64 - RT*r.
    int bid = blockIdx.x, r = 0, rowcnt;
    while (bid >= (rowcnt = n64 - RT * r)) { bid -= rowcnt; r++; }
    const int i0 = r * TI;
    const int j0 = (RT * r + bid) * TJ;
    const bool band = (j0 < i0 + TI);

    // Stage j tile (negated t and p; masked/OOB p -> NaN).
    if (tid < TJ) {
        int j = j0 + tid;
        float tj = 0.f, pj = NANF;
        if (j < B) {
            tj = t[j];
            if (m[j] != 0) pj = p[j];
        }
        float* f = reinterpret_cast<float*>(sj);
        f[2 * tid]     = -tj;
        f[2 * tid + 1] = -pj;
    }
    __syncthreads();

    // i rows (NaN-folded p). The j0==i0 block of each row counts mask bits.
    float ti[NI], pi[NI];
    int lcnt = 0;
#pragma unroll
    for (int q = 0; q < NI; q++) {
        int i = i0 + q * BI + tid;
        ti[q] = 0.f;
        pi[q] = NANF;
        if (i < B) {
            ti[q] = t[i];
            if (m[i] != 0) { pi[q] = p[i]; lcnt++; }
        }
    }
    if (j0 != i0) lcnt = 0;

    float acc[2 * NI];
#pragma unroll
    for (int k = 0; k < 2 * NI; k++) acc[k] = 0.f;

#pragma unroll 8
    for (int k = 0; k < TJ / 2; k++) {
        float4 v = sj[k];   // {-t0, -p0, -t1, -p1}
#pragma unroll
        for (int q = 0; q < NI; q++) {
            float dt0 = ti[q] + v.x;
            float dp0 = pi[q] + v.y;
            acc[2 * q]     += fminf(sign_mul(dp0, dt0), MARGIN);
            float dt1 = ti[q] + v.z;
            float dp1 = pi[q] + v.w;
            acc[2 * q + 1] += fminf(sign_mul(dp1, dt1), MARGIN);
        }
    }

    float lsum = 0.f;
#pragma unroll
    for (int k = 0; k < 2 * NI; k++) lsum += acc[k];
    if (!band) lsum *= 2.0f;    // strictly-upper tiles stand for both orders

#pragma unroll
    for (int off = 16; off > 0; off >>= 1) {
        lsum += __shfl_down_sync(0xFFFFFFFFu, lsum, off);
        lcnt += __shfl_down_sync(0xFFFFFFFFu, lcnt, off);
    }
    const int wid = tid >> 5, lid = tid & 31;
    if (lid == 0) { red_s[wid] = lsum; red_c[wid] = lcnt; }
    __syncthreads();

    const int nparts = gridDim.x;
    if (wid == 0) {
        constexpr int NW = BI / 32;
        float bs = (lid < NW) ? red_s[lid] : 0.f;
        int   bc = (lid < NW) ? red_c[lid] : 0;
#pragma unroll
        for (int off = 16; off > 0; off >>= 1) {
            bs += __shfl_down_sync(0xFFFFFFFFu, bs, off);
            bc += __shfl_down_sync(0xFFFFFFFFu, bc, off);
        }
        if (lid == 0) {
            g_part[blockIdx.x] = bs;
            if (bc) atomicAdd(&g_cnt, bc);
            __threadfence();
            unsigned int d = atomicAdd(&g_done, 1u);
            s_is_last = (d == (unsigned)(nparts - 1));
        }
    }
    __syncthreads();

    // Last block: reduce partials, apply analytic corrections, reset state.
    if (s_is_last) {
        double s = 0.0;
        for (int k = tid; k < nparts; k += BI) s += (double)g_part[k];
#pragma unroll
        for (int off = 16; off > 0; off >>= 1)
            s += __shfl_down_sync(0xFFFFFFFFu, s, off);
        __shared__ double rds[BI / 32];
        if (lid == 0) rds[wid] = s;
        __syncthreads();
        if (wid == 0) {
            constexpr int NW = BI / 32;
            double bs = (lid < NW) ? rds[lid] : 0.0;
#pragma unroll
            for (int off = 16; off > 0; off >>= 1)
                bs += __shfl_down_sync(0xFFFFFFFFu, bs, off);
            if (lid == 0) {
                double nv = (double)g_cnt;
                double N  = (double)(n64 * TJ);       // padded square dimension
                double sum = (double)MARGIN * (N * N - nv) - bs;
                double cnt = nv * (nv - 1.0);
                if (cnt < 1.0) cnt = 1.0;
                out[0] = (float)(sum / cnt);
                g_done = 0u;   // reset for next graph replay
                g_cnt = 0;
            }
        }
    }
}

extern "C" void kernel_launch(void* const* d_in, const int* in_sizes, int n_in,
                              void* d_out, int out_size) {
    const float* p = (const float*)d_in[0];
    const float* t = (const float*)d_in[1];
    const int*   m = (const int*)d_in[2];
    float* out = (float*)d_out;
    const int B = in_sizes[0];

    const int nt  = (B + TI - 1) / TI;     // i tiles
    const int n64 = nt * RT;               // j tiles across padded width
    int nblocks = 0;
    for (int r = 0; r < nt; r++) nblocks += n64 - RT * r;

    mrl_pair<<<nblocks, BI>>>(p, t, m, B, n64, out);
}

// round 11
// speedup vs baseline: 1.3375x; 1.3375x over previous
#include <cuda_runtime.h>
#include <cuda_fp16.h>
#include <cstdint>

#define MARGIN 0.1f
#define NANF_U 0x7fffffffu

#define TI 512    // i per block (NI * BI)
#define TJ 64     // j per block
#define BI 256    // threads
#define NI 2      // i rows per thread
#define RT (TI / TJ)   // band width in j-tiles per i-tile row = 8

// Cross-block state; last block resets g_done/g_cnt each launch (graph-safe).
__device__ float        g_part[4096];
__device__ int          g_cnt;
__device__ unsigned int g_done;

__device__ __forceinline__ unsigned h2u(__half2 h) {
    return *reinterpret_cast<unsigned*>(&h);
}
__device__ __forceinline__ __half2 u2h(unsigned u) {
    return *reinterpret_cast<__half2*>(&u);
}

// Triangle-tiled sweep (validated R7-R10). fp16x2 body: each instruction
// evaluates 2 j's. Per 2 pairs: HADD2 dt, HADD2 dp, LOP3 sign-fold
// (mask 0x80008000), HMIN2 (minNum: NaN -> margin), HADD2 acc.
//  valid pair -> min(s, m_h); masked/OOB (p=NaN) -> m_h; unmasked diag -> 0.
// sum_hinge = m_h*(N*N - nv) - A, count = nv*(nv-1), with m_h the fp16-exact
// margin so the invalid-slot cancellation is exact.
__global__ void __launch_bounds__(BI, 7)
mrl_pair(const float* __restrict__ p,
         const float* __restrict__ t,
         const int* __restrict__ m,
         int B, int n64, float* __restrict__ out) {
    // j tile as half: group g of 4 j's = 16B: {t0,t1, p0,p1, t2,t3, p2,p3}
    __shared__ __half sh[TJ * 2];
    __shared__ float red_s[BI / 32];
    __shared__ int   red_c[BI / 32];
    __shared__ int   s_is_last;

    const int tid = threadIdx.x;
    const float NANF = __uint_as_float(NANF_U);

    // Decode linear block id -> (i-tile r, j-tile). Row r owns n64 - RT*r.
    int bid = blockIdx.x, r = 0, rowcnt;
    while (bid >= (rowcnt = n64 - RT * r)) { bid -= rowcnt; r++; }
    const int i0 = r * TI;
    const int j0 = (RT * r + bid) * TJ;
    const bool band = (j0 < i0 + TI);

    // Stage j tile (negated, fp16, masked/OOB p -> NaN).
    if (tid < TJ) {
        int j = j0 + tid;
        float tj = 0.f, pj = NANF;
        if (j < B) {
            tj = t[j];
            if (m[j] != 0) pj = p[j];
        }
        int g = tid >> 2, q = tid & 3;
        sh[8 * g + (q >> 1) * 4 + (q & 1)]     = __float2half_rn(-tj);
        sh[8 * g + (q >> 1) * 4 + (q & 1) + 2] = __float2half_rn(-pj);
    }
    __syncthreads();

    // i rows, broadcast to half2. The j0==i0 block of each row counts mask.
    __half2 ti2[NI], pi2[NI];
    int lcnt = 0;
#pragma unroll
    for (int q = 0; q < NI; q++) {
        int i = i0 + q * BI + tid;
        float tif = 0.f, pif = NANF;
        if (i < B) {
            tif = t[i];
            if (m[i] != 0) { pif = p[i]; lcnt++; }
        }
        ti2[q] = __half2half2(__float2half_rn(tif));
        pi2[q] = __half2half2(__float2half_rn(pif));
    }
    if (j0 != i0) lcnt = 0;

    const __half2 m2 = __half2half2(__float2half_rn(MARGIN));
    __half2 acc[2 * NI];
#pragma unroll
    for (int k = 0; k < 2 * NI; k++) acc[k] = __half2half2(__ushort_as_half(0));

    const uint4* sj4 = reinterpret_cast<const uint4*>(sh);
#pragma unroll
    for (int k = 0; k < TJ / 4; k++) {
        uint4 w = sj4[k];   // {t01, p01, t23, p23} negated halves
#pragma unroll
        for (int q = 0; q < NI; q++) {
            __half2 dta = __hadd2(ti2[q], u2h(w.x));
            __half2 dpa = __hadd2(pi2[q], u2h(w.y));
            unsigned sa = h2u(dpa) ^ (h2u(dta) & 0x80008000u);
            acc[2 * q] = __hadd2(acc[2 * q], __hmin2(u2h(sa), m2));
            __half2 dtb = __hadd2(ti2[q], u2h(w.z));
            __half2 dpb = __hadd2(pi2[q], u2h(w.w));
            unsigned sb = h2u(dpb) ^ (h2u(dtb) & 0x80008000u);
            acc[2 * q + 1] = __hadd2(acc[2 * q + 1], __hmin2(u2h(sb), m2));
        }
    }

    float lsum = 0.f;
#pragma unroll
    for (int k = 0; k < 2 * NI; k++)
        lsum += __low2float(acc[k]) + __high2float(acc[k]);
    if (!band) lsum *= 2.0f;    // strictly-upper tiles stand for both orders

#pragma unroll
    for (int off = 16; off > 0; off >>= 1) {
        lsum += __shfl_down_sync(0xFFFFFFFFu, lsum, off);
        lcnt += __shfl_down_sync(0xFFFFFFFFu, lcnt, off);
    }
    const int wid = tid >> 5, lid = tid & 31;
    if (lid == 0) { red_s[wid] = lsum; red_c[wid] = lcnt; }
    __syncthreads();

    const int nparts = gridDim.x;
    if (wid == 0) {
        constexpr int NW = BI / 32;
        float bs = (lid < NW) ? red_s[lid] : 0.f;
        int   bc = (lid < NW) ? red_c[lid] : 0;
#pragma unroll
        for (int off = 16; off > 0; off >>= 1) {
            bs += __shfl_down_sync(0xFFFFFFFFu, bs, off);
            bc += __shfl_down_sync(0xFFFFFFFFu, bc, off);
        }
        if (lid == 0) {
            g_part[blockIdx.x] = bs;
            if (bc) atomicAdd(&g_cnt, bc);
            __threadfence();
            unsigned int d = atomicAdd(&g_done, 1u);
            s_is_last = (d == (unsigned)(nparts - 1));
        }
    }
    __syncthreads();

    // Last block: reduce partials, apply analytic corrections, reset state.
    if (s_is_last) {
        double s = 0.0;
        for (int k = tid; k < nparts; k += BI) s += (double)g_part[k];
#pragma unroll
        for (int off = 16; off > 0; off >>= 1)
            s += __shfl_down_sync(0xFFFFFFFFu, s, off);
        __shared__ double rds[BI / 32];
        if (lid == 0) rds[wid] = s;
        __syncthreads();
        if (wid == 0) {
            constexpr int NW = BI / 32;
            double bs = (lid < NW) ? rds[lid] : 0.0;
#pragma unroll
            for (int off = 16; off > 0; off >>= 1)
                bs += __shfl_down_sync(0xFFFFFFFFu, bs, off);
            if (lid == 0) {
                double nv = (double)g_cnt;
                double N  = (double)(n64 * TJ);       // padded square dimension
                // fp16-exact margin so invalid-slot cancellation is exact
                double mh = (double)__half2float(__float2half_rn(MARGIN));
                double sum = mh * (N * N - nv) - bs;
                double cnt = nv * (nv - 1.0);
                if (cnt < 1.0) cnt = 1.0;
                out[0] = (float)(sum / cnt);
                g_done = 0u;   // reset for next graph replay
                g_cnt = 0;
            }
        }
    }
}

extern "C" void kernel_launch(void* const* d_in, const int* in_sizes, int n_in,
                              void* d_out, int out_size) {
    const float* p = (const float*)d_in[0];
    const float* t = (const float*)d_in[1];
    const int*   m = (const int*)d_in[2];
    float* out = (float*)d_out;
    const int B = in_sizes[0];

    const int nt  = (B + TI - 1) / TI;     // i tiles
    const int n64 = nt * RT;               // j tiles across padded width
    int nblocks = 0;
    for (int r = 0; r < nt; r++) nblocks += n64 - RT * r;

    mrl_pair<<<nblocks, BI>>>(p, t, m, B, n64, out);
}